// round 9
// baseline (speedup 1.0000x reference)
#include <cuda_runtime.h>

#define WIDTH 4096
#define DEPTH 32
typedef unsigned long long ull;

// theta table: g_theta4[(t*4+j)*256 + tid] = (cos,sin,cos,sin) for k=2j, 2j+1
// lane-dense: consecutive tid = consecutive float4 -> dense LDG.128
__device__ float4 g_theta4[32 * 4 * 256];

static __device__ __forceinline__ ull pack2(float lo, float hi) {
    ull r; asm("mov.b64 %0, {%1,%2};" : "=l"(r) : "f"(lo), "f"(hi)); return r;
}
static __device__ __forceinline__ void unpack2(ull v, float &lo, float &hi) {
    asm("mov.b64 {%0,%1}, %2;" : "=f"(lo), "=f"(hi) : "l"(v));
}
static __device__ __forceinline__ ull mul2(ull a, ull b) {
    ull r; asm("mul.rn.f32x2 %0, %1, %2;" : "=l"(r) : "l"(a), "l"(b)); return r;
}
static __device__ __forceinline__ ull fma2(ull a, ull b, ull c) {
    ull r; asm("fma.rn.f32x2 %0, %1, %2, %3;" : "=l"(r) : "l"(a), "l"(b), "l"(c)); return r;
}

// logical column u from (pattern, register slot cr, thread id)
// pat 0: u[11:8]=cr   pat 1: u[7:4]=cr   pat 2: u[3:0]=cr
static __device__ __forceinline__ int asmU_rt(int pat, int cr, int tid) {
    if (pat == 0) return (cr << 8) | tid;
    if (pat == 1) return (cr << 4) | (tid & 15) | ((tid & 0xF0) << 4);
    return cr | ((tid & 15) << 4) | ((tid & 0xF0) << 4);
}
template<int PAT> static __device__ __forceinline__ int asmU(int cr, int tid) {
    return asmU_rt(PAT, cr, tid);
}
// swizzle over 8B smem words: low nibble -> cr^ln^wp, injective per half-warp
// in every pattern -> conflict-free STS.64/LDS.64
static __device__ __forceinline__ int swz(int u) {
    return u ^ (((u >> 4) ^ (u >> 8)) & 15);
}

__global__ void bfly_theta_kernel(const float* __restrict__ params) {
    int idx = blockIdx.x * blockDim.x + threadIdx.x;   // 65536 float2 slots
    int t   = idx >> 11;
    int j   = (idx >> 9) & 3;
    int tid = (idx >> 1) & 255;
    int h   = idx & 1;
    int k   = 2 * j + h;
    int pat = (t >> 2) % 3;
    int m   = 3 - (t & 3);                                   // reg bit for stage
    int i0  = ((k >> m) << (m + 1)) | (k & ((1 << m) - 1));  // pair slot, bit m=0
    int u   = asmU_rt(pat, i0, tid);
    int s   = t % 12;
    int ur  = s ? (((u << s) | (u >> (12 - s))) & 4095) : u; // rotl12(u,t)
    float th = params[(ur & 2047) * DEPTH + t];
    float c, sn;
    sincosf(th, &sn, &c);
    ((float2*)g_theta4)[idx] = make_float2(c, sn);   // idx = 2*((t*4+j)*256+tid)+h
}

static __device__ __forceinline__ void stage_load(float4 q[4], int t, int tid) {
    const float4* th = g_theta4 + (t << 10) + tid;
#pragma unroll
    for (int j = 0; j < 4; j++) q[j] = __ldg(th + (j << 8));
}

template<int M>
static __device__ __forceinline__ void stage_compute(ull d[16], const float4 q[4]) {
#pragma unroll
    for (int j = 0; j < 4; j++) {
#pragma unroll
        for (int h = 0; h < 2; h++) {
            int k = 2 * j + h;
            float c = h ? q[j].z : q[j].x;
            float s = h ? q[j].w : q[j].y;
            ull cc = pack2(c, c);
            ull ss = pack2(s, s);
            ull ns = ss ^ 0x8000000080000000ULL;   // (-s,-s)
            int i0 = ((k >> M) << (M + 1)) | (k & ((1 << M) - 1));
            int i1 = i0 | (1 << M);
            ull x0 = d[i0], x1 = d[i1];
            d[i0] = fma2(x0, cc, mul2(x1, ss));   // y0 =  c*x0 + s*x1
            d[i1] = fma2(x0, ns, mul2(x1, cc));   // y1 = -s*x0 + c*x1
        }
    }
}

template<int PO, int PN>
static __device__ __forceinline__ void xpose(ull d[16], int tid, ull* sm) {
#pragma unroll
    for (int cr = 0; cr < 16; cr++)
        sm[swz(asmU<PO>(cr, tid))] = d[cr];
    __syncthreads();
#pragma unroll
    for (int cr = 0; cr < 16; cr++)
        d[cr] = sm[swz(asmU<PN>(cr, tid))];
    __syncthreads();
}

// prefetch stage t+1 theta into B, then run stage t from A
#define STEP(t, A, B)                       \
    stage_load(B, (t) + 1, tid);            \
    stage_compute<3 - ((t) & 3)>(d, A);

__global__ __launch_bounds__(256, 4)
void bfly_main_kernel(const float* __restrict__ X, float* __restrict__ out) {
    __shared__ ull sm[4096];            // 32KB/CTA -> 4 CTAs/SM
    int tid = threadIdx.x;
    size_t row0 = (size_t)blockIdx.x * 2;
    const float* x = X + row0 * WIDTH;
    float* o = out + row0 * WIDTH;

    float4 qa[4], qb[4];
    stage_load(qa, 0, tid);             // prefetch stage 0 behind input loads

    ull d[16];                          // d[cr] = rows (0,1) packed, column u
#pragma unroll
    for (int cr = 0; cr < 16; cr++) {   // pattern-0 load, lane-dense
        int u = (cr << 8) | tid;
        d[cr] = pack2(x[u], x[WIDTH + u]);
    }

    STEP(0, qa, qb)  STEP(1, qb, qa)  STEP(2, qa, qb)  STEP(3, qb, qa)
    xpose<0, 1>(d, tid, sm);
    STEP(4, qa, qb)  STEP(5, qb, qa)  STEP(6, qa, qb)  STEP(7, qb, qa)
    xpose<1, 2>(d, tid, sm);
    STEP(8, qa, qb)  STEP(9, qb, qa)  STEP(10, qa, qb) STEP(11, qb, qa)
    xpose<2, 0>(d, tid, sm);
    STEP(12, qa, qb) STEP(13, qb, qa) STEP(14, qa, qb) STEP(15, qb, qa)
    xpose<0, 1>(d, tid, sm);
    STEP(16, qa, qb) STEP(17, qb, qa) STEP(18, qa, qb) STEP(19, qb, qa)
    xpose<1, 2>(d, tid, sm);
    STEP(20, qa, qb) STEP(21, qb, qa) STEP(22, qa, qb) STEP(23, qb, qa)
    xpose<2, 0>(d, tid, sm);
    STEP(24, qa, qb) STEP(25, qb, qa) STEP(26, qa, qb) STEP(27, qb, qa)
    xpose<0, 1>(d, tid, sm);
    STEP(28, qa, qb) STEP(29, qb, qa) STEP(30, qa, qb)
    stage_compute<0>(d, qb);            // stage 31, no prefetch

    // regs in pattern 1 over u; output col o = rotl12(u,8)
    //   = (tid[3:0]<<8) | (tid[7:4]<<4) | cr  -> 16 CONSECUTIVE cols per thread.
    // Direct store: 2 rows x 4 STG.128, no smem round, no barrier.
    int obase = ((tid & 15) << 8) | ((tid >> 4) << 4);
#pragma unroll
    for (int r = 0; r < 2; r++) {
        float4* op = (float4*)(o + (size_t)r * WIDTH + obase);
#pragma unroll
        for (int j = 0; j < 4; j++) {
            float lo0, hi0, lo1, hi1, lo2, hi2, lo3, hi3;
            unpack2(d[4 * j + 0], lo0, hi0);
            unpack2(d[4 * j + 1], lo1, hi1);
            unpack2(d[4 * j + 2], lo2, hi2);
            unpack2(d[4 * j + 3], lo3, hi3);
            float4 w;
            w.x = r ? hi0 : lo0;
            w.y = r ? hi1 : lo1;
            w.z = r ? hi2 : lo2;
            w.w = r ? hi3 : lo3;
            op[j] = w;
        }
    }
}

extern "C" void kernel_launch(void* const* d_in, const int* in_sizes, int n_in,
                              void* d_out, int out_size) {
    const float* X = (const float*)d_in[0];
    const float* params = (const float*)d_in[1];
    if (n_in >= 2 && in_sizes[0] == 2048 * 32) {  // guard against input-order swap
        X = (const float*)d_in[1];
        params = (const float*)d_in[0];
    }
    bfly_theta_kernel<<<256, 256>>>(params);
    bfly_main_kernel<<<8192, 256>>>(X, (float*)d_out);
}

// round 12
// speedup vs baseline: 1.5069x; 1.5069x over previous
#include <cuda_runtime.h>

#define WIDTH 4096
#define DEPTH 32
typedef unsigned long long ull;

// Phase patterns: nibble positions (0=[3:0],1=[7:4],2=[11:8]) of
// R = register index cr, A = tid[3:0], B = tid[7:4], for phases 0..7:
//   R: 2 1 0 2 1 0 2 1
//   A: 0 0 1 1 2 2 0 0
//   B: 1 2 2 0 0 1 1 2
// Boundaries: B1,B3,B5,B7 = smem (cr<->wp), B2,B4,B6 = warp shuffle (cr<->ln).
template<int PH> struct Pat {
    static constexpr int R = (PH == 0) ? 2 : (PH == 1) ? 1 : (PH == 2) ? 0
                           : (PH == 3) ? 2 : (PH == 4) ? 1 : (PH == 5) ? 0
                           : (PH == 6) ? 2 : 1;
    static constexpr int A = (PH == 0) ? 0 : (PH == 1) ? 0 : (PH == 2) ? 1
                           : (PH == 3) ? 1 : (PH == 4) ? 2 : (PH == 5) ? 2
                           : (PH == 6) ? 0 : 0;
    static constexpr int B = (PH == 0) ? 1 : (PH == 1) ? 2 : (PH == 2) ? 2
                           : (PH == 3) ? 0 : (PH == 4) ? 0 : (PH == 5) ? 1
                           : (PH == 6) ? 1 : 2;
};

// theta table: g_theta4[(t*4+j)*256 + tid] = (cos,sin,cos,sin) for k=2j, 2j+1
// lane-dense: consecutive tid = consecutive float4 -> dense LDG.128
__device__ float4 g_theta4[32 * 4 * 256];

static __device__ __forceinline__ ull pack2(float lo, float hi) {
    ull r; asm("mov.b64 %0, {%1,%2};" : "=l"(r) : "f"(lo), "f"(hi)); return r;
}
static __device__ __forceinline__ void unpack2(ull v, float &lo, float &hi) {
    asm("mov.b64 {%0,%1}, %2;" : "=f"(lo), "=f"(hi) : "l"(v));
}
static __device__ __forceinline__ ull mul2(ull a, ull b) {
    ull r; asm("mul.rn.f32x2 %0, %1, %2;" : "=l"(r) : "l"(a), "l"(b)); return r;
}
static __device__ __forceinline__ ull fma2(ull a, ull b, ull c) {
    ull r; asm("fma.rn.f32x2 %0, %1, %2, %3;" : "=l"(r) : "l"(a), "l"(b), "l"(c)); return r;
}

template<int PH>
static __device__ __forceinline__ int asmU(int cr, int tid) {
    return (cr << (4 * Pat<PH>::R)) | ((tid & 15) << (4 * Pat<PH>::A))
         | ((tid >> 4) << (4 * Pat<PH>::B));
}
// runtime version (theta precompute only)
static __device__ __forceinline__ int asmU_rt(int ph, int cr, int tid) {
    const int Rl[8] = {2, 1, 0, 2, 1, 0, 2, 1};
    const int Al[8] = {0, 0, 1, 1, 2, 2, 0, 0};
    const int Bl[8] = {1, 2, 2, 0, 0, 1, 1, 2};
    return (cr << (4 * Rl[ph])) | ((tid & 15) << (4 * Al[ph]))
         | ((tid >> 4) << (4 * Bl[ph]));
}
// swizzle over 16B smem words; slot bits = cr^ln^wp in every pattern ->
// conflict-free STS.128/LDS.128 in both directions of every smem transpose
static __device__ __forceinline__ int swz(int u) {
    return u ^ (((u >> 4) ^ (u >> 8)) & 15);
}

__global__ void bfly_theta_kernel(const float* __restrict__ params) {
    int idx = blockIdx.x * blockDim.x + threadIdx.x;   // 65536 float2 slots
    int t   = idx >> 11;
    int j   = (idx >> 9) & 3;
    int tid = (idx >> 1) & 255;
    int h   = idx & 1;
    int k   = 2 * j + h;
    int ph  = t >> 2;
    int m   = 3 - (t & 3);                                   // reg bit for stage
    int i0  = ((k >> m) << (m + 1)) | (k & ((1 << m) - 1));  // pair slot, bit m=0
    int u   = asmU_rt(ph, i0, tid);
    int s   = t % 12;
    int ur  = s ? (((u << s) | (u >> (12 - s))) & 4095) : u; // rotl12(u,t)
    float th = params[(ur & 2047) * DEPTH + t];
    float c, sn;
    sincosf(th, &sn, &c);
    ((float2*)g_theta4)[idx] = make_float2(c, sn);   // idx = 2*((t*4+j)*256+tid)+h
}

static __device__ __forceinline__ void stage_load(float4 q[4], int t, int tid) {
    const float4* th = g_theta4 + (t << 10) + tid;
#pragma unroll
    for (int j = 0; j < 4; j++) q[j] = __ldg(th + (j << 8));
}

template<int M>
static __device__ __forceinline__ void stage_compute(ull d[32], const float4 q[4]) {
#pragma unroll
    for (int j = 0; j < 4; j++) {
#pragma unroll
        for (int h = 0; h < 2; h++) {
            int k = 2 * j + h;
            float c = h ? q[j].z : q[j].x;
            float s = h ? q[j].w : q[j].y;
            ull cc = pack2(c, c);
            ull ss = pack2(s, s);
            ull ns = ss ^ 0x8000000080000000ULL;   // (-s,-s)
            int i0 = ((k >> M) << (M + 1)) | (k & ((1 << M) - 1));
            int i1 = i0 | (1 << M);
#pragma unroll
            for (int rp = 0; rp < 2; rp++) {
                ull x0 = d[2 * i0 + rp], x1 = d[2 * i1 + rp];
                d[2 * i0 + rp] = fma2(x0, cc, mul2(x1, ss));   // y0 =  c*x0 + s*x1
                d[2 * i1 + rp] = fma2(x0, ns, mul2(x1, cc));   // y1 = -s*x0 + c*x1
            }
        }
    }
}

// smem transpose between phases PHO -> PHN (pure cr <-> tid[7:4] exchange)
template<int PHO, int PHN>
static __device__ __forceinline__ void xpose(ull d[32], int tid, longlong2* sm) {
#pragma unroll
    for (int cr = 0; cr < 16; cr++)
        sm[swz(asmU<PHO>(cr, tid))] =
            make_longlong2((long long)d[2 * cr], (long long)d[2 * cr + 1]);
    __syncthreads();
#pragma unroll
    for (int cr = 0; cr < 16; cr++) {
        longlong2 v = sm[swz(asmU<PHN>(cr, tid))];
        d[2 * cr] = (ull)v.x;
        d[2 * cr + 1] = (ull)v.y;
    }
    __syncthreads();
}

// Warp-shuffle transpose: exchange register nibble cr with lane nibble
// tid[3:0]. 4 butterfly rounds, all register indices compile-time.
static __device__ __forceinline__ void shfl_xpose(ull d[32], int tid) {
    int ln = tid & 15;
#pragma unroll
    for (int i = 0; i < 4; i++) {
        bool p = (ln >> i) & 1;
#pragma unroll
        for (int c0 = 0; c0 < 16; c0++) {
            if (c0 & (1 << i)) continue;      // c0 has bit i clear
            int c1 = c0 | (1 << i);
#pragma unroll
            for (int rp = 0; rp < 2; rp++) {
                ull v = p ? d[2 * c0 + rp] : d[2 * c1 + rp];
                v = __shfl_xor_sync(0xFFFFFFFFu, v, 1 << i);
                if (p) d[2 * c0 + rp] = v; else d[2 * c1 + rp] = v;
            }
        }
    }
}

// row r (0..3) of column-register cr
static __device__ __forceinline__ float getv(const ull d[32], int cr, int r) {
    float lo, hi;
    unpack2(d[2 * cr + (r >> 1)], lo, hi);
    return (r & 1) ? hi : lo;
}

// prefetch stage t+1 theta into B, then run stage t from A
#define STEP(t, A, B)                       \
    stage_load(B, (t) + 1, tid);            \
    stage_compute<3 - ((t) & 3)>(d, A);

__global__ __launch_bounds__(256, 2)
void bfly_main_kernel(const float* __restrict__ X, float* __restrict__ out) {
    extern __shared__ longlong2 sm[];   // 4096 x 16B = 64KB
    int tid = threadIdx.x;
    size_t row0 = (size_t)blockIdx.x * 4;
    const float* x = X + row0 * WIDTH;
    float* o = out + row0 * WIDTH;

    float4 qa[4], qb[4];
    stage_load(qa, 0, tid);             // prefetch stage 0 behind input loads

    ull d[32];  // [cr*2+rp]: rp0 = rows(0,1) packed, rp1 = rows(2,3) packed
#pragma unroll
    for (int cr = 0; cr < 16; cr++) {   // phase-0 load (R2 A0 B1), lane-dense
        int u = (cr << 8) | tid;
        d[2 * cr]     = pack2(x[u],             x[WIDTH + u]);
        d[2 * cr + 1] = pack2(x[2 * WIDTH + u], x[3 * WIDTH + u]);
    }

    // ph1 (stages 0-3)
    STEP(0, qa, qb)  STEP(1, qb, qa)  STEP(2, qa, qb)  STEP(3, qb, qa)
    xpose<0, 1>(d, tid, sm);            // B1: smem
    // ph2 (4-7)
    STEP(4, qa, qb)  STEP(5, qb, qa)  STEP(6, qa, qb)  STEP(7, qb, qa)
    shfl_xpose(d, tid);                 // B2: shuffle
    // ph3 (8-11)
    STEP(8, qa, qb)  STEP(9, qb, qa)  STEP(10, qa, qb) STEP(11, qb, qa)
    xpose<2, 3>(d, tid, sm);            // B3: smem
    // ph4 (12-15)
    STEP(12, qa, qb) STEP(13, qb, qa) STEP(14, qa, qb) STEP(15, qb, qa)
    shfl_xpose(d, tid);                 // B4: shuffle
    // ph5 (16-19)
    STEP(16, qa, qb) STEP(17, qb, qa) STEP(18, qa, qb) STEP(19, qb, qa)
    xpose<4, 5>(d, tid, sm);            // B5: smem
    // ph6 (20-23)
    STEP(20, qa, qb) STEP(21, qb, qa) STEP(22, qa, qb) STEP(23, qb, qa)
    shfl_xpose(d, tid);                 // B6: shuffle
    // ph7 (24-27)
    STEP(24, qa, qb) STEP(25, qb, qa) STEP(26, qa, qb) STEP(27, qb, qa)
    xpose<6, 7>(d, tid, sm);            // B7: smem
    // ph8 (28-31)
    STEP(28, qa, qb) STEP(29, qb, qa) STEP(30, qa, qb)
    stage_compute<0>(d, qb);            // stage 31, no prefetch

    // ph8 layout (R1 A0 B2): u = (tid>>4)<<8 | cr<<4 | (tid&15).
    // Output col o = rotl12(u,8) = (tid[3:0]<<8)|(tid[7:4]<<4)|cr ->
    // 16 CONSECUTIVE cols per thread: direct 4x4 STG.128, no smem, no barrier.
    int obase = ((tid & 15) << 8) | ((tid >> 4) << 4);
#pragma unroll
    for (int r = 0; r < 4; r++) {
        float4* op = (float4*)(o + (size_t)r * WIDTH + obase);
#pragma unroll
        for (int j = 0; j < 4; j++) {
            float4 w;
            w.x = getv(d, 4 * j + 0, r);
            w.y = getv(d, 4 * j + 1, r);
            w.z = getv(d, 4 * j + 2, r);
            w.w = getv(d, 4 * j + 3, r);
            op[j] = w;
        }
    }
}

extern "C" void kernel_launch(void* const* d_in, const int* in_sizes, int n_in,
                              void* d_out, int out_size) {
    const float* X = (const float*)d_in[0];
    const float* params = (const float*)d_in[1];
    if (n_in >= 2 && in_sizes[0] == 2048 * 32) {  // guard against input-order swap
        X = (const float*)d_in[1];
        params = (const float*)d_in[0];
    }
    cudaFuncSetAttribute(bfly_main_kernel,
                         cudaFuncAttributeMaxDynamicSharedMemorySize, 65536);
    bfly_theta_kernel<<<256, 256>>>(params);
    bfly_main_kernel<<<4096, 256, 65536>>>(X, (float*)d_out);
}

// round 13
// speedup vs baseline: 1.6947x; 1.1246x over previous
#include <cuda_runtime.h>

#define WIDTH 4096
#define DEPTH 32
typedef unsigned long long ull;

// theta table: g_theta4[(t*4+j)*256 + tid] = (cos,sin,cos,sin) for k=2j, 2j+1
// lane-dense: consecutive tid = consecutive float4 -> dense LDG.128
__device__ float4 g_theta4[32 * 4 * 256];

static __device__ __forceinline__ ull pack2(float lo, float hi) {
    ull r; asm("mov.b64 %0, {%1,%2};" : "=l"(r) : "f"(lo), "f"(hi)); return r;
}
static __device__ __forceinline__ void unpack2(ull v, float &lo, float &hi) {
    asm("mov.b64 {%0,%1}, %2;" : "=f"(lo), "=f"(hi) : "l"(v));
}
static __device__ __forceinline__ ull mul2(ull a, ull b) {
    ull r; asm("mul.rn.f32x2 %0, %1, %2;" : "=l"(r) : "l"(a), "l"(b)); return r;
}
static __device__ __forceinline__ ull fma2(ull a, ull b, ull c) {
    ull r; asm("fma.rn.f32x2 %0, %1, %2, %3;" : "=l"(r) : "l"(a), "l"(b), "l"(c)); return r;
}

// logical column u from (pattern, register slot cr, thread id) — r6 3-cycle
// pat 0: u[11:8]=cr   pat 1: u[7:4]=cr   pat 2: u[3:0]=cr
template<int PAT>
static __device__ __forceinline__ int asmU(int cr, int tid) {
    return (PAT == 0) ? ((cr << 8) | tid)
         : (PAT == 1) ? ((cr << 4) | (tid & 15) | ((tid & 0xF0) << 4))
                      : (cr | ((tid & 15) << 4) | ((tid & 0xF0) << 4));
}
static __device__ __forceinline__ int asmU_rt(int pat, int cr, int tid) {
    if (pat == 0) return (cr << 8) | tid;
    if (pat == 1) return (cr << 4) | (tid & 15) | ((tid & 0xF0) << 4);
    return cr | ((tid & 15) << 4) | ((tid & 0xF0) << 4);
}
// swizzle over 16B smem words; slot bits = cr^ln^wp -> conflict-free always
static __device__ __forceinline__ int swz(int u) {
    return u ^ (((u >> 4) ^ (u >> 8)) & 15);
}

__global__ void bfly_theta_kernel(const float* __restrict__ params) {
    int idx = blockIdx.x * blockDim.x + threadIdx.x;   // 65536 float2 slots
    int t   = idx >> 11;
    int j   = (idx >> 9) & 3;
    int tid = (idx >> 1) & 255;
    int h   = idx & 1;
    int k   = 2 * j + h;
    int pat = (t >> 2) % 3;
    int m   = 3 - (t & 3);                                   // reg bit for stage
    int i0  = ((k >> m) << (m + 1)) | (k & ((1 << m) - 1));  // pair slot, bit m=0
    int u   = asmU_rt(pat, i0, tid);
    int s   = t % 12;
    int ur  = s ? (((u << s) | (u >> (12 - s))) & 4095) : u; // rotl12(u,t)
    float th = params[(ur & 2047) * DEPTH + t];
    float c, sn;
    sincosf(th, &sn, &c);
    ((float2*)g_theta4)[idx] = make_float2(c, sn);   // idx = 2*((t*4+j)*256+tid)+h
}

static __device__ __forceinline__ void stage_load(float4 q[4], int t, int tid) {
    const float4* th = g_theta4 + (t << 10) + tid;
#pragma unroll
    for (int j = 0; j < 4; j++) q[j] = __ldg(th + (j << 8));
}

// butterfly on register pair (i0,i1), both row-pairs
static __device__ __forceinline__ void bfly(ull d[32], int i0, int i1,
                                            float c, float s) {
    ull cc = pack2(c, c);
    ull ss = pack2(s, s);
    ull ns = ss ^ 0x8000000080000000ULL;   // (-s,-s)
#pragma unroll
    for (int rp = 0; rp < 2; rp++) {
        ull x0 = d[2 * i0 + rp], x1 = d[2 * i1 + rp];
        d[2 * i0 + rp] = fma2(x0, cc, mul2(x1, ss));   // y0 =  c*x0 + s*x1
        d[2 * i1 + rp] = fma2(x0, ns, mul2(x1, cc));   // y1 = -s*x0 + c*x1
    }
}

template<int M>
static __device__ __forceinline__ void stage_compute(ull d[32], const float4 q[4]) {
#pragma unroll
    for (int j = 0; j < 4; j++) {
#pragma unroll
        for (int h = 0; h < 2; h++) {
            int k = 2 * j + h;
            int i0 = ((k >> M) << (M + 1)) | (k & ((1 << M) - 1));
            bfly(d, i0, i0 | (1 << M), h ? q[j].z : q[j].x, h ? q[j].w : q[j].y);
        }
    }
}

// FUSED: last stage of a phase (M=0, pairs (2k,2k+1)) + immediate STS of the
// finished pair. STS issues overlap the remaining butterflies.
template<int PAT>
static __device__ __forceinline__ void last_sts(ull d[32], const float4 q[4],
                                                int tid, longlong2* sm) {
#pragma unroll
    for (int j = 0; j < 4; j++) {
#pragma unroll
        for (int h = 0; h < 2; h++) {
            int k = 2 * j + h;
            int i0 = 2 * k, i1 = 2 * k + 1;
            bfly(d, i0, i1, h ? q[j].z : q[j].x, h ? q[j].w : q[j].y);
            sm[swz(asmU<PAT>(i0, tid))] =
                make_longlong2((long long)d[2 * i0], (long long)d[2 * i0 + 1]);
            sm[swz(asmU<PAT>(i1, tid))] =
                make_longlong2((long long)d[2 * i1], (long long)d[2 * i1 + 1]);
        }
    }
}

// FUSED: LDS of new-pattern registers + first stage of the phase (M=3,
// pairs (k,k+8)). Compute starts after 4 loads instead of 16.
template<int PAT>
static __device__ __forceinline__ void first_lds(ull d[32], const float4 q[4],
                                                 int tid, longlong2* sm) {
#pragma unroll
    for (int j = 0; j < 4; j++) {
        int kA = 2 * j, kB = 2 * j + 1;
        longlong2 a0 = sm[swz(asmU<PAT>(kA,     tid))];
        longlong2 a1 = sm[swz(asmU<PAT>(kA + 8, tid))];
        longlong2 b0 = sm[swz(asmU<PAT>(kB,     tid))];
        longlong2 b1 = sm[swz(asmU<PAT>(kB + 8, tid))];
        d[2 * kA]           = (ull)a0.x; d[2 * kA + 1]       = (ull)a0.y;
        d[2 * (kA + 8)]     = (ull)a1.x; d[2 * (kA + 8) + 1] = (ull)a1.y;
        d[2 * kB]           = (ull)b0.x; d[2 * kB + 1]       = (ull)b0.y;
        d[2 * (kB + 8)]     = (ull)b1.x; d[2 * (kB + 8) + 1] = (ull)b1.y;
        bfly(d, kA, kA + 8, q[j].x, q[j].y);
        bfly(d, kB, kB + 8, q[j].z, q[j].w);
    }
}

// row r (0..3) of column-register cr
static __device__ __forceinline__ float getv(const ull d[32], int cr, int r) {
    float lo, hi;
    unpack2(d[2 * cr + (r >> 1)], lo, hi);
    return (r & 1) ? hi : lo;
}

__global__ __launch_bounds__(256, 2)
void bfly_main_kernel(const float* __restrict__ X, float* __restrict__ out) {
    extern __shared__ longlong2 sm[];   // 4096 x 16B = 64KB
    int tid = threadIdx.x;
    size_t row0 = (size_t)blockIdx.x * 4;
    const float* x = X + row0 * WIDTH;
    float* o = out + row0 * WIDTH;

    float4 qa[4], qb[4];
    stage_load(qa, 0, tid);             // prefetch stage 0 behind input loads

    ull d[32];  // [cr*2+rp]: rp0 = rows(0,1) packed, rp1 = rows(2,3) packed
#pragma unroll
    for (int cr = 0; cr < 16; cr++) {   // pattern-0 load, lane-dense
        int u = (cr << 8) | tid;
        d[2 * cr]     = pack2(x[u],             x[WIDTH + u]);
        d[2 * cr + 1] = pack2(x[2 * WIDTH + u], x[3 * WIDTH + u]);
    }

    // ---- ph0 (pat0, stages 0-3) ----
    stage_load(qb, 1, tid);  stage_compute<3>(d, qa);
    stage_load(qa, 2, tid);  stage_compute<2>(d, qb);
    stage_load(qb, 3, tid);  stage_compute<1>(d, qa);
    stage_load(qa, 4, tid);  last_sts<0>(d, qb, tid, sm);   // s3 + STS(pat0)
    __syncthreads();
    // ---- ph1 (pat1, 4-7) ----
    stage_load(qb, 5, tid);  first_lds<1>(d, qa, tid, sm);  // LDS(pat1) + s4
    stage_load(qa, 6, tid);  stage_compute<2>(d, qb);
    stage_load(qb, 7, tid);  stage_compute<1>(d, qa);
    stage_load(qa, 8, tid);  __syncthreads();               // pre-store bar
    last_sts<1>(d, qb, tid, sm);                            // s7 + STS(pat1)
    __syncthreads();
    // ---- ph2 (pat2, 8-11) ----
    stage_load(qb, 9, tid);  first_lds<2>(d, qa, tid, sm);  // s8
    stage_load(qa, 10, tid); stage_compute<2>(d, qb);
    stage_load(qb, 11, tid); stage_compute<1>(d, qa);
    stage_load(qa, 12, tid); __syncthreads();
    last_sts<2>(d, qb, tid, sm);                            // s11 + STS(pat2)
    __syncthreads();
    // ---- ph3 (pat0, 12-15) ----
    stage_load(qb, 13, tid); first_lds<0>(d, qa, tid, sm);  // s12
    stage_load(qa, 14, tid); stage_compute<2>(d, qb);
    stage_load(qb, 15, tid); stage_compute<1>(d, qa);
    stage_load(qa, 16, tid); __syncthreads();
    last_sts<0>(d, qb, tid, sm);                            // s15
    __syncthreads();
    // ---- ph4 (pat1, 16-19) ----
    stage_load(qb, 17, tid); first_lds<1>(d, qa, tid, sm);  // s16
    stage_load(qa, 18, tid); stage_compute<2>(d, qb);
    stage_load(qb, 19, tid); stage_compute<1>(d, qa);
    stage_load(qa, 20, tid); __syncthreads();
    last_sts<1>(d, qb, tid, sm);                            // s19
    __syncthreads();
    // ---- ph5 (pat2, 20-23) ----
    stage_load(qb, 21, tid); first_lds<2>(d, qa, tid, sm);  // s20
    stage_load(qa, 22, tid); stage_compute<2>(d, qb);
    stage_load(qb, 23, tid); stage_compute<1>(d, qa);
    stage_load(qa, 24, tid); __syncthreads();
    last_sts<2>(d, qb, tid, sm);                            // s23
    __syncthreads();
    // ---- ph6 (pat0, 24-27) ----
    stage_load(qb, 25, tid); first_lds<0>(d, qa, tid, sm);  // s24
    stage_load(qa, 26, tid); stage_compute<2>(d, qb);
    stage_load(qb, 27, tid); stage_compute<1>(d, qa);
    stage_load(qa, 28, tid); __syncthreads();
    last_sts<0>(d, qb, tid, sm);                            // s27
    __syncthreads();
    // ---- ph7 (pat1, 28-31) ----
    stage_load(qb, 29, tid); first_lds<1>(d, qa, tid, sm);  // s28
    stage_load(qa, 30, tid); stage_compute<2>(d, qb);       // s29
    stage_load(qb, 31, tid); stage_compute<1>(d, qa);       // s30
    stage_compute<0>(d, qb);                                // s31 (no STS)

    // pat1 layout: u = (tid>>4)<<8 | cr<<4 | (tid&15); output col
    // o = rotl12(u,8) = (tid[3:0]<<8)|(tid[7:4]<<4)|cr -> 16 CONSECUTIVE
    // cols per thread: direct 4x4 STG.128, no smem, no barrier.
    int obase = ((tid & 15) << 8) | ((tid >> 4) << 4);
#pragma unroll
    for (int r = 0; r < 4; r++) {
        float4* op = (float4*)(o + (size_t)r * WIDTH + obase);
#pragma unroll
        for (int j = 0; j < 4; j++) {
            float4 w;
            w.x = getv(d, 4 * j + 0, r);
            w.y = getv(d, 4 * j + 1, r);
            w.z = getv(d, 4 * j + 2, r);
            w.w = getv(d, 4 * j + 3, r);
            op[j] = w;
        }
    }
}

extern "C" void kernel_launch(void* const* d_in, const int* in_sizes, int n_in,
                              void* d_out, int out_size) {
    const float* X = (const float*)d_in[0];
    const float* params = (const float*)d_in[1];
    if (n_in >= 2 && in_sizes[0] == 2048 * 32) {  // guard against input-order swap
        X = (const float*)d_in[1];
        params = (const float*)d_in[0];
    }
    cudaFuncSetAttribute(bfly_main_kernel,
                         cudaFuncAttributeMaxDynamicSharedMemorySize, 65536);
    bfly_theta_kernel<<<256, 256>>>(params);
    bfly_main_kernel<<<4096, 256, 65536>>>(X, (float*)d_out);
}